// round 1
// baseline (speedup 1.0000x reference)
#include <cuda_runtime.h>
#include <math.h>

#define BB 256
#define HH 1024
#define UU 1024
#define CC 512
#define KK 10
#define NCHUNK 8
#define UC (UU / NCHUNK)   // 128 u-rows per chunk

// Scratch (device globals — no allocation allowed)
__device__ float g_alpha[BB * KK];
__device__ float g_beta[BB * KK];
__device__ float g_partial[NCHUNK * BB * CC];   // 4 MB partial windows

__device__ __forceinline__ float softplus_f(float x) {
    // logaddexp(x, 0) = max(x,0) + log1p(exp(-|x|)) — stable, matches jax.nn.softplus
    return fmaxf(x, 0.0f) + log1pf(expf(-fabsf(x)));
}

// ---------------------------------------------------------------------------
// Kernel 1: params = h @ W^T + b, then activations.
// One warp per (b, j) output, j in [0, 30). 7680 warps = 960 blocks of 256.
// float4 loads, stride-32 across lanes (coalesced); W rows hit L2 (120 KB).
// ---------------------------------------------------------------------------
__global__ void k_params(const float* __restrict__ h,
                         const float* __restrict__ W,
                         const float* __restrict__ bias,
                         const float* __restrict__ k_prev,
                         float* __restrict__ out_kappa) {
    int w = (blockIdx.x * blockDim.x + threadIdx.x) >> 5;
    int lane = threadIdx.x & 31;
    if (w >= BB * 30) return;
    int b = w / 30;
    int j = w % 30;

    const float4* h4 = (const float4*)(h + (size_t)b * HH);
    const float4* w4 = (const float4*)(W + (size_t)j * HH);
    float s = 0.0f;
#pragma unroll
    for (int i = 0; i < 8; i++) {                 // 8 * 32 lanes * 4 = 1024
        float4 a = h4[i * 32 + lane];
        float4 c = w4[i * 32 + lane];
        s += a.x * c.x + a.y * c.y + a.z * c.z + a.w * c.w;
    }
#pragma unroll
    for (int off = 16; off; off >>= 1)
        s += __shfl_xor_sync(0xffffffffu, s, off);

    if (lane == 0) {
        s += bias[j];
        if (j < KK) {
            g_alpha[b * KK + j] = softplus_f(s) + 1e-4f;
        } else if (j < 2 * KK) {
            g_beta[b * KK + (j - KK)] = fminf(fmaxf(softplus_f(s), 0.1f), 10.0f);
        } else {
            int k = j - 2 * KK;
            out_kappa[b * KK + k] = k_prev[b * KK + k] + softplus_f(s) * 0.1f;
        }
    }
}

// ---------------------------------------------------------------------------
// Kernel 2: phi[b,u] = sum_k alpha * exp(-beta * (kappa - u)^2).
// One thread per (b,u). Param loads are warp-uniform -> L1 broadcast.
// ---------------------------------------------------------------------------
__global__ void k_phi(const float* __restrict__ kappa,
                      float* __restrict__ phi_out) {
    int idx = blockIdx.x * blockDim.x + threadIdx.x;   // [0, B*U)
    int b = idx >> 10;        // / U
    int u = idx & (UU - 1);
    float uf = (float)u;
    float s = 0.0f;
#pragma unroll
    for (int k = 0; k < KK; k++) {
        float a  = g_alpha[b * KK + k];
        float be = g_beta[b * KK + k];
        float ka = kappa[b * KK + k];
        float d = ka - uf;
        s += a * __expf(-be * d * d);
    }
    phi_out[idx] = s;
}

// ---------------------------------------------------------------------------
// Kernel 3: partial windows. grid = (NCHUNK, B), 128 threads.
// Each block: one batch b, one u-chunk of 128 rows; thread t owns float4
// column group t of C=512. Fully coalesced 2 KB-row float4 loads.
// 2048 blocks x 128 threads — entire grid resident in one wave on 148 SMs.
// ---------------------------------------------------------------------------
__global__ void k_window_partial(const float* __restrict__ phi,
                                 const float* __restrict__ c_seq) {
    __shared__ float phs[UC];
    int chunk = blockIdx.x;
    int b     = blockIdx.y;
    int t     = threadIdx.x;       // 0..127
    int u0    = chunk * UC;

    phs[t] = phi[b * UU + u0 + t];     // UC == blockDim.x == 128
    __syncthreads();

    const float4* cs = (const float4*)c_seq + (size_t)(b * UU + u0) * (CC / 4) + t;
    float4 acc = make_float4(0.f, 0.f, 0.f, 0.f);
#pragma unroll 4
    for (int u = 0; u < UC; u++) {
        float4 v = cs[(size_t)u * (CC / 4)];
        float p = phs[u];
        acc.x += p * v.x;
        acc.y += p * v.y;
        acc.z += p * v.z;
        acc.w += p * v.w;
    }
    ((float4*)g_partial)[(size_t)(chunk * BB + b) * (CC / 4) + t] = acc;
}

// ---------------------------------------------------------------------------
// Kernel 4: reduce 8 partials -> window. Fixed summation order (deterministic).
// ---------------------------------------------------------------------------
__global__ void k_reduce(float* __restrict__ win) {
    int i = blockIdx.x * blockDim.x + threadIdx.x;   // over B*C/4 float4s
    const float4* p = (const float4*)g_partial;
    float4 s = p[i];
#pragma unroll
    for (int c = 1; c < NCHUNK; c++) {
        float4 v = p[c * (BB * CC / 4) + i];
        s.x += v.x; s.y += v.y; s.z += v.z; s.w += v.w;
    }
    ((float4*)win)[i] = s;
}

// ---------------------------------------------------------------------------
// Launch: inputs per metadata order: h, c_seq, k_prev, W, b.
// Output tuple (window[B,C], phi[B,U], kappa[B,K]) packed in that order.
// ---------------------------------------------------------------------------
extern "C" void kernel_launch(void* const* d_in, const int* in_sizes, int n_in,
                              void* d_out, int out_size) {
    const float* h      = (const float*)d_in[0];
    const float* c_seq  = (const float*)d_in[1];
    const float* k_prev = (const float*)d_in[2];
    const float* W      = (const float*)d_in[3];
    const float* bias   = (const float*)d_in[4];

    float* out  = (float*)d_out;
    float* win  = out;                       // [B, C]
    float* phi  = out + BB * CC;             // [B, U]
    float* kap  = out + BB * CC + BB * UU;   // [B, K]

    // 1) params + activations: 7680 warps
    k_params<<<(BB * 30 * 32 + 255) / 256, 256>>>(h, W, bias, k_prev, kap);

    // 2) phi: 262144 threads
    k_phi<<<(BB * UU) / 256, 256>>>(kap, phi);

    // 3) partial windows: (8, 256) blocks x 128 threads — reads the 512 MB
    dim3 g3(NCHUNK, BB);
    k_window_partial<<<g3, UC>>>(phi, c_seq);

    // 4) final reduce: 131072 outputs as float4
    k_reduce<<<(BB * CC / 4) / 256, 256>>>(win);
}

// round 2
// speedup vs baseline: 1.0726x; 1.0726x over previous
#include <cuda_runtime.h>
#include <math.h>

#define BB 256
#define HH 1024
#define UU 1024
#define CC 512
#define KK 10
#define NCHUNK 8
#define UC (UU / NCHUNK)   // 128 u-rows per chunk

// Scratch (device globals — no allocation allowed)
__device__ float g_alpha[BB * KK];
__device__ float g_beta[BB * KK];
__device__ float g_partial[NCHUNK * BB * CC];     // 4 MB partial windows
__device__ unsigned int g_ticket[BB];             // zero-init; reset by last block

__device__ __forceinline__ float softplus_f(float x) {
    // max(x,0) + log1p(exp(-|x|)) — stable, matches jax.nn.softplus
    return fmaxf(x, 0.0f) + log1pf(expf(-fabsf(x)));
}

// ---------------------------------------------------------------------------
// Kernel 1: params = h @ W^T + b, then activations.
// One warp per (b, j) output, j in [0, 30). 7680 warps.
// ---------------------------------------------------------------------------
__global__ void k_params(const float* __restrict__ h,
                         const float* __restrict__ W,
                         const float* __restrict__ bias,
                         const float* __restrict__ k_prev,
                         float* __restrict__ out_kappa) {
    int w = (blockIdx.x * blockDim.x + threadIdx.x) >> 5;
    int lane = threadIdx.x & 31;
    if (w >= BB * 30) return;
    int b = w / 30;
    int j = w % 30;

    const float4* h4 = (const float4*)(h + (size_t)b * HH);
    const float4* w4 = (const float4*)(W + (size_t)j * HH);
    float s = 0.0f;
#pragma unroll
    for (int i = 0; i < 8; i++) {                 // 8 * 32 lanes * 4 = 1024
        float4 a = h4[i * 32 + lane];
        float4 c = w4[i * 32 + lane];
        s += a.x * c.x + a.y * c.y + a.z * c.z + a.w * c.w;
    }
#pragma unroll
    for (int off = 16; off; off >>= 1)
        s += __shfl_xor_sync(0xffffffffu, s, off);

    if (lane == 0) {
        s += bias[j];
        if (j < KK) {
            g_alpha[b * KK + j] = softplus_f(s) + 1e-4f;
        } else if (j < 2 * KK) {
            g_beta[b * KK + (j - KK)] = fminf(fmaxf(softplus_f(s), 0.1f), 10.0f);
        } else {
            int k = j - 2 * KK;
            out_kappa[b * KK + k] = k_prev[b * KK + k] + softplus_f(s) * 0.1f;
        }
    }
}

// ---------------------------------------------------------------------------
// Kernel 2 (fused): phi + partial window + last-block reduce.
// grid = (NCHUNK, B), 128 threads. Thread t:
//   - computes phi[b, u0+t] from alpha/beta/kappa (writes phi output + smem)
//   - accumulates float4 column-group t over its 128 u-rows (reads 512 MB total)
//   - last block per batch (atomic ticket) reduces the 8 partials in fixed
//     chunk order (deterministic) and writes window[b].
// ---------------------------------------------------------------------------
__global__ void k_window(const float* __restrict__ kappa,
                         const float* __restrict__ c_seq,
                         float* __restrict__ phi_out,
                         float* __restrict__ win) {
    __shared__ float phs[UC];
    int chunk = blockIdx.x;
    int b     = blockIdx.y;
    int t     = threadIdx.x;       // 0..127
    int u0    = chunk * UC;

    // --- phi for this block's u-rows (broadcast param loads) ---
    {
        float uf = (float)(u0 + t);
        float s = 0.0f;
#pragma unroll
        for (int k = 0; k < KK; k++) {
            float a  = g_alpha[b * KK + k];
            float be = g_beta[b * KK + k];
            float ka = kappa[b * KK + k];
            float d = ka - uf;
            s += a * __expf(-be * d * d);
        }
        phs[t] = s;
        phi_out[b * UU + u0 + t] = s;
    }
    __syncthreads();

    // --- partial window: streaming read of c_seq chunk ---
    const float4* cs = (const float4*)c_seq + (size_t)(b * UU + u0) * (CC / 4) + t;
    float4 acc = make_float4(0.f, 0.f, 0.f, 0.f);
#pragma unroll 8
    for (int u = 0; u < UC; u++) {
        float4 v = __ldcs(&cs[(size_t)u * (CC / 4)]);
        float p = phs[u];
        acc.x += p * v.x;
        acc.y += p * v.y;
        acc.z += p * v.z;
        acc.w += p * v.w;
    }
    ((float4*)g_partial)[(size_t)(chunk * BB + b) * (CC / 4) + t] = acc;

    // --- last-block-done reduce (deterministic fixed chunk order) ---
    __threadfence();
    __shared__ unsigned int is_last;
    __syncthreads();
    if (t == 0)
        is_last = (atomicAdd(&g_ticket[b], 1u) == NCHUNK - 1) ? 1u : 0u;
    __syncthreads();

    if (is_last) {
        const float4* p = (const float4*)g_partial;
        float4 s = p[(size_t)(0 * BB + b) * (CC / 4) + t];
#pragma unroll
        for (int c = 1; c < NCHUNK; c++) {
            float4 v = p[(size_t)(c * BB + b) * (CC / 4) + t];
            s.x += v.x; s.y += v.y; s.z += v.z; s.w += v.w;
        }
        ((float4*)win)[(size_t)b * (CC / 4) + t] = s;
        if (t == 0) g_ticket[b] = 0;   // reset for next graph replay
    }
}

// ---------------------------------------------------------------------------
// Launch: inputs per metadata order: h, c_seq, k_prev, W, b.
// Output tuple (window[B,C], phi[B,U], kappa[B,K]) packed in that order.
// ---------------------------------------------------------------------------
extern "C" void kernel_launch(void* const* d_in, const int* in_sizes, int n_in,
                              void* d_out, int out_size) {
    const float* h      = (const float*)d_in[0];
    const float* c_seq  = (const float*)d_in[1];
    const float* k_prev = (const float*)d_in[2];
    const float* W      = (const float*)d_in[3];
    const float* bias   = (const float*)d_in[4];

    float* out  = (float*)d_out;
    float* win  = out;                       // [B, C]
    float* phi  = out + BB * CC;             // [B, U]
    float* kap  = out + BB * CC + BB * UU;   // [B, K]

    // 1) params + activations
    k_params<<<(BB * 30 * 32 + 255) / 256, 256>>>(h, W, bias, k_prev, kap);

    // 2) fused phi + window partial + reduce: reads the 512 MB
    dim3 g2(NCHUNK, BB);
    k_window<<<g2, UC>>>(kap, c_seq, phi, win);
}